// round 5
// baseline (speedup 1.0000x reference)
#include <cuda_runtime.h>
#include <math.h>

// Problem constants (fixed by reference)
#define B_    8
#define S_    4096
#define E_    768
#define H_    12
#define D_    64
#define M_TOT (B_ * S_)      // 32768
#define N_QKV (3 * E_)       // 2304
#define SCH   4              // s-chunks for split-S kv pass

typedef unsigned long long ull;

// Scratch (allocation-free rule: __device__ globals)
__device__ float g_qkv[(size_t)M_TOT * N_QKV];    // 288 MB: [B*S, 3E]  q|k(elu+1)|v
__device__ float g_attn[(size_t)M_TOT * E_];      //  96 MB: [B*S, E]   pre-proj
__device__ float g_kv[B_ * H_ * D_ * D_];         // [bh, d, e]
__device__ float g_ksum[B_ * H_ * D_];            // [bh, d]
__device__ float g_kvp[SCH][B_ * H_ * D_ * D_];   // partial kv per s-chunk
__device__ float g_ksp[SCH][B_ * H_ * D_];        // partial ksum per s-chunk

// ---- packed fp32x2 helpers (SASS FFMA2 — 2x FMA throughput, full fp32) ----
__device__ __forceinline__ ull pack2dup(float v) {
    ull r;
    asm("mov.b64 %0, {%1, %1};" : "=l"(r) : "f"(v));
    return r;
}
__device__ __forceinline__ void ffma2(ull& d, ull a, ull b) {
    asm("fma.rn.f32x2 %0, %1, %2, %0;" : "+l"(d) : "l"(a), "l"(b));
}
__device__ __forceinline__ float2 unpack2(ull v) {
    float2 f;
    asm("mov.b64 {%0, %1}, %2;" : "=f"(f.x), "=f"(f.y) : "l"(v));
    return f;
}

// ---------------------------------------------------------------------------
// fp32 GEMM with packed FFMA2: C[M,N] = A[M,K] @ B[K,N].
// 128x128 tile, BK=16, 256 threads, 8x8 microtile held as 8x4 f32x2 pairs.
// A staged in smem DUPLICATED ((a,a) pairs); double-buffered smem:
//   LDG(tile t+1) -> compute(buf t) -> STS(buf t+1) -> one __syncthreads.
// Epilogue: one STG.128 per row-half. MODE 1: elu(c)+1 on cols < 2E.
// MODE 2: c += bias[col]. All dims divide the tiles exactly.
// ---------------------------------------------------------------------------
template <int MODE>
__global__ __launch_bounds__(256) void sgemm_kernel(
    int M, int N, int K,
    const float* __restrict__ A, const float* __restrict__ Bm,
    const float* __restrict__ bias, float* __restrict__ C)
{
    constexpr int BM = 128, BN = 128, BK = 16;
    __shared__ float As2[2][BK][2 * BM];  // duplicated: [buf][k][2m]=[buf][k][2m+1]
    __shared__ float Bs[2][BK][BN];

    const int tid = threadIdx.x;
    const int m0 = blockIdx.y * BM;
    const int n0 = blockIdx.x * BN;
    const int ty = tid >> 4;       // 0..15 -> rows ty*8..ty*8+7
    const int tx = tid & 15;       // 0..15 -> cols {tx*4..+3} U {64+tx*4..+3}

    const int ar0 = tid >> 2, ac4 = tid & 3;   // A: rows ar0 / ar0+64, k-cols ac4*4..+3
    const int br0 = tid >> 5, bc4 = tid & 31;  // B: k-rows br0 / br0+8, cols bc4*4..+3

    const float* Ap0 = A + (size_t)(m0 + ar0) * K + ac4 * 4;
    const float* Ap1 = A + (size_t)(m0 + ar0 + 64) * K + ac4 * 4;
    const float* Bp0 = Bm + (size_t)br0 * N + n0 + bc4 * 4;
    const float* Bp1 = Bm + (size_t)(br0 + 8) * N + n0 + bc4 * 4;

    ull acc[8][4];
#pragma unroll
    for (int i = 0; i < 8; i++)
#pragma unroll
        for (int j = 0; j < 4; j++) acc[i][j] = 0ull;

    // ---- prologue: load tile 0 and stage into buf 0 ----
    {
        float4 a0 = *(const float4*)(Ap0);
        float4 a1 = *(const float4*)(Ap1);
        float4 b0 = *(const float4*)(Bp0);
        float4 b1 = *(const float4*)(Bp1);
        *(ull*)&As2[0][ac4 * 4 + 0][2 * ar0] = pack2dup(a0.x);
        *(ull*)&As2[0][ac4 * 4 + 1][2 * ar0] = pack2dup(a0.y);
        *(ull*)&As2[0][ac4 * 4 + 2][2 * ar0] = pack2dup(a0.z);
        *(ull*)&As2[0][ac4 * 4 + 3][2 * ar0] = pack2dup(a0.w);
        *(ull*)&As2[0][ac4 * 4 + 0][2 * (ar0 + 64)] = pack2dup(a1.x);
        *(ull*)&As2[0][ac4 * 4 + 1][2 * (ar0 + 64)] = pack2dup(a1.y);
        *(ull*)&As2[0][ac4 * 4 + 2][2 * (ar0 + 64)] = pack2dup(a1.z);
        *(ull*)&As2[0][ac4 * 4 + 3][2 * (ar0 + 64)] = pack2dup(a1.w);
        *(float4*)&Bs[0][br0][bc4 * 4] = b0;
        *(float4*)&Bs[0][br0 + 8][bc4 * 4] = b1;
    }
    __syncthreads();

    const int ntiles = K / BK;
    for (int t = 0; t < ntiles; t++) {
        const int cur = t & 1, nxt = cur ^ 1;
        float4 a0, a1, b0, b1;
        const bool more = (t + 1 < ntiles);
        if (more) {                     // issue LDG for tile t+1 before compute
            const int k0 = (t + 1) * BK;
            a0 = *(const float4*)(Ap0 + k0);
            a1 = *(const float4*)(Ap1 + k0);
            b0 = *(const float4*)(Bp0 + (size_t)k0 * N);
            b1 = *(const float4*)(Bp1 + (size_t)k0 * N);
        }

#pragma unroll
        for (int k = 0; k < BK; k++) {
            const ulonglong2* ap = (const ulonglong2*)&As2[cur][k][ty * 16];
            ulonglong2 A01 = ap[0], A23 = ap[1], A45 = ap[2], A67 = ap[3];
            ulonglong2 B01 = *(const ulonglong2*)&Bs[cur][k][tx * 4];
            ulonglong2 B23 = *(const ulonglong2*)&Bs[cur][k][tx * 4 + 64];
            ull au[8] = {A01.x, A01.y, A23.x, A23.y, A45.x, A45.y, A67.x, A67.y};
            ull bu[4] = {B01.x, B01.y, B23.x, B23.y};
#pragma unroll
            for (int i = 0; i < 8; i++)
#pragma unroll
                for (int j = 0; j < 4; j++)
                    ffma2(acc[i][j], au[i], bu[j]);
        }

        if (more) {                     // stage t+1 into the other buffer
            *(ull*)&As2[nxt][ac4 * 4 + 0][2 * ar0] = pack2dup(a0.x);
            *(ull*)&As2[nxt][ac4 * 4 + 1][2 * ar0] = pack2dup(a0.y);
            *(ull*)&As2[nxt][ac4 * 4 + 2][2 * ar0] = pack2dup(a0.z);
            *(ull*)&As2[nxt][ac4 * 4 + 3][2 * ar0] = pack2dup(a0.w);
            *(ull*)&As2[nxt][ac4 * 4 + 0][2 * (ar0 + 64)] = pack2dup(a1.x);
            *(ull*)&As2[nxt][ac4 * 4 + 1][2 * (ar0 + 64)] = pack2dup(a1.y);
            *(ull*)&As2[nxt][ac4 * 4 + 2][2 * (ar0 + 64)] = pack2dup(a1.z);
            *(ull*)&As2[nxt][ac4 * 4 + 3][2 * (ar0 + 64)] = pack2dup(a1.w);
            *(float4*)&Bs[nxt][br0][bc4 * 4] = b0;
            *(float4*)&Bs[nxt][br0 + 8][bc4 * 4] = b1;
            __syncthreads();
        }
    }

    // ---- epilogue: per row-half, 2 contiguous f32x2 pairs -> one STG.128 ----
#pragma unroll
    for (int i = 0; i < 8; i++) {
        const int row = m0 + ty * 8 + i;
        float* crow = C + (size_t)row * N;
#pragma unroll
        for (int half = 0; half < 2; half++) {
            const int col = n0 + tx * 4 + half * 64;
            float2 c0 = unpack2(acc[i][half * 2 + 0]);   // cols col, col+1
            float2 c1 = unpack2(acc[i][half * 2 + 1]);   // cols col+2, col+3
            if (MODE == 1) {
                if (col < 2 * E_) {        // boundary (1536) is 4-col aligned
                    c0.x = (c0.x > 0.f) ? (c0.x + 1.f) : __expf(c0.x);
                    c0.y = (c0.y > 0.f) ? (c0.y + 1.f) : __expf(c0.y);
                    c1.x = (c1.x > 0.f) ? (c1.x + 1.f) : __expf(c1.x);
                    c1.y = (c1.y > 0.f) ? (c1.y + 1.f) : __expf(c1.y);
                }
            }
            if (MODE == 2) {
                const float4 bv = *(const float4*)(bias + col);
                c0.x += bv.x; c0.y += bv.y; c1.x += bv.z; c1.y += bv.w;
            }
            float4 o; o.x = c0.x; o.y = c0.y; o.z = c1.x; o.w = c1.y;
            *(float4*)(crow + col) = o;
        }
    }
}

// ---------------------------------------------------------------------------
// Pass 1: partial kv/ksum per (bh, s-chunk).  Grid (B*H, SCH), 256 thr.
// kvp[sc][bh,d,e] = sum_{s in chunk} k[bh,s,d]*v[bh,s,e]; same for ksum.
// ---------------------------------------------------------------------------
__global__ __launch_bounds__(256) void kv_partial_kernel(const float* __restrict__ qkv)
{
    __shared__ float Ks[64][64];
    __shared__ float Vs[64][64];

    const int bh = blockIdx.x;
    const int sc = blockIdx.y;
    const int b = bh / H_, h = bh % H_;
    const int tid = threadIdx.x;
    const int ty = tid >> 4, tx = tid & 15;

    const float* kbase = qkv + (size_t)b * S_ * N_QKV + E_ + h * D_;
    const float* vbase = kbase + E_;

    float acc[4][4] = {};
    float ks[4] = {0.f, 0.f, 0.f, 0.f};

    const int s_beg = sc * (S_ / SCH), s_end = s_beg + S_ / SCH;
    for (int s0 = s_beg; s0 < s_end; s0 += 64) {
        __syncthreads();
#pragma unroll
        for (int i = 0; i < 4; i++) {
            int idx = tid + i * 256;
            int row = idx >> 4, c4 = idx & 15;
            *(float4*)&Ks[row][c4 * 4] =
                *(const float4*)(kbase + (size_t)(s0 + row) * N_QKV + c4 * 4);
            *(float4*)&Vs[row][c4 * 4] =
                *(const float4*)(vbase + (size_t)(s0 + row) * N_QKV + c4 * 4);
        }
        __syncthreads();
#pragma unroll 8
        for (int s = 0; s < 64; s++) {
            float4 av = *(float4*)&Ks[s][ty * 4];
            float4 bv = *(float4*)&Vs[s][tx * 4];
            float a[4] = {av.x, av.y, av.z, av.w};
            float bb[4] = {bv.x, bv.y, bv.z, bv.w};
            if (tx == 0) { ks[0] += a[0]; ks[1] += a[1]; ks[2] += a[2]; ks[3] += a[3]; }
#pragma unroll
            for (int i = 0; i < 4; i++)
#pragma unroll
                for (int j = 0; j < 4; j++)
                    acc[i][j] = fmaf(a[i], bb[j], acc[i][j]);
        }
    }

    float* kvp = g_kvp[sc] + (size_t)bh * D_ * D_;
#pragma unroll
    for (int i = 0; i < 4; i++)
#pragma unroll
        for (int j = 0; j < 4; j++)
            kvp[(ty * 4 + i) * D_ + tx * 4 + j] = acc[i][j];
    if (tx == 0) {
#pragma unroll
        for (int i = 0; i < 4; i++) g_ksp[sc][bh * D_ + ty * 4 + i] = ks[i];
    }
}

// ---------------------------------------------------------------------------
// Pass 2: reduce partials -> g_kv, g_ksum, and the tuple-tail kv output.
// Grid (B*H), 256 thr; each thread reduces 16 of the 4096 kv elements.
// ---------------------------------------------------------------------------
__global__ __launch_bounds__(256) void kv_reduce_kernel(
    float* __restrict__ out_tail, int write_tail)
{
    const int bh = blockIdx.x;
    const int tid = threadIdx.x;
    const size_t base = (size_t)bh * D_ * D_;

#pragma unroll
    for (int i = 0; i < 4; i++) {                // 256 thr * 4 float4 = 4096
        const int off = (tid + i * 256) * 4;
        float4 s = *(const float4*)(g_kvp[0] + base + off);
#pragma unroll
        for (int c = 1; c < SCH; c++) {
            float4 p = *(const float4*)(g_kvp[c] + base + off);
            s.x += p.x; s.y += p.y; s.z += p.z; s.w += p.w;
        }
        *(float4*)(g_kv + base + off) = s;
        if (write_tail) *(float4*)(out_tail + base + off) = s;
    }
    if (tid < D_) {
        float s = 0.f;
#pragma unroll
        for (int c = 0; c < SCH; c++) s += g_ksp[c][bh * D_ + tid];
        g_ksum[bh * D_ + tid] = s;
    }
}

// ---------------------------------------------------------------------------
// attn[b,s,h*64+e] = z[b,h,s] * sum_d q[bh,s,d]*kv[bh,d,e],
// z = 1/(q . ksum). Block = (b,h) x 64 s-rows. 256 thr, 2x8 microtile.
// ---------------------------------------------------------------------------
__global__ __launch_bounds__(256) void attn_kernel(const float* __restrict__ qkv)
{
    __shared__ float Qs[64][65];     // +1 pad: conflict-free Qs[r][k] column reads
    __shared__ float kvs[64][64];
    __shared__ float ksums[64];
    __shared__ float zs[64];

    const int bh = blockIdx.x;
    const int b = bh / H_, h = bh % H_;
    const int s0 = blockIdx.y * 64;
    const int tid = threadIdx.x;

    const float* qbase = qkv + (size_t)b * S_ * N_QKV + h * D_;

#pragma unroll
    for (int i = 0; i < 4; i++) {                 // Q tile 64x64
        int idx = tid + i * 256;
        int row = idx >> 4, c4 = idx & 15;
        float4 v = *(const float4*)(qbase + (size_t)(s0 + row) * N_QKV + c4 * 4);
        Qs[row][c4 * 4 + 0] = v.x; Qs[row][c4 * 4 + 1] = v.y;
        Qs[row][c4 * 4 + 2] = v.z; Qs[row][c4 * 4 + 3] = v.w;
    }
#pragma unroll
    for (int i = 0; i < 4; i++) {                 // kv 64x64
        int idx = tid + i * 256;
        int row = idx >> 4, c4 = idx & 15;
        *(float4*)&kvs[row][c4 * 4] =
            *(const float4*)(g_kv + (size_t)bh * 4096 + row * 64 + c4 * 4);
    }
    if (tid < 16)
        ((float4*)ksums)[tid] = ((const float4*)(g_ksum + bh * 64))[tid];
    __syncthreads();

    if (tid < 64) {                               // z per s-row
        float dot = 0.f;
#pragma unroll
        for (int k = 0; k < 64; k++) dot = fmaf(Qs[tid][k], ksums[k], dot);
        zs[tid] = 1.f / dot;                      // denom strictly positive (q,k > 0)
    }
    __syncthreads();

    const int ty = tid >> 3;   // 0..31 -> 2 rows each
    const int tx = tid & 7;    // 0..7  -> 8 cols each
    float acc[2][8] = {};
#pragma unroll 8
    for (int k = 0; k < 64; k++) {
        float a0 = Qs[ty * 2 + 0][k];
        float a1 = Qs[ty * 2 + 1][k];
        float4 bv0 = *(float4*)&kvs[k][tx * 8];
        float4 bv1 = *(float4*)&kvs[k][tx * 8 + 4];
        float bb[8] = {bv0.x, bv0.y, bv0.z, bv0.w, bv1.x, bv1.y, bv1.z, bv1.w};
#pragma unroll
        for (int j = 0; j < 8; j++) {
            acc[0][j] = fmaf(a0, bb[j], acc[0][j]);
            acc[1][j] = fmaf(a1, bb[j], acc[1][j]);
        }
    }

    float* obase = g_attn + (size_t)(b * S_ + s0) * E_ + h * D_;
#pragma unroll
    for (int i = 0; i < 2; i++) {
        int r = ty * 2 + i;
        float z = zs[r];
#pragma unroll
        for (int j = 0; j < 8; j++)
            obase[(size_t)r * E_ + tx * 8 + j] = acc[i][j] * z;
    }
}

// ---------------------------------------------------------------------------
extern "C" void kernel_launch(void* const* d_in, const int* in_sizes, int n_in,
                              void* d_out, int out_size)
{
    const float* x      = (const float*)d_in[0];   // [B,S,E]
    const float* w_qkv  = (const float*)d_in[1];   // [E,3E]
    const float* w_proj = (const float*)d_in[2];   // [E,E]
    const float* b_proj = (const float*)d_in[3];   // [E]
    float* out = (float*)d_out;

    float *p_qkv = nullptr, *p_attn = nullptr;
    cudaGetSymbolAddress((void**)&p_qkv, g_qkv);
    cudaGetSymbolAddress((void**)&p_attn, g_attn);

    // 1) qkv GEMM + fused elu(.)+1 on q,k columns
    dim3 g1(N_QKV / 128, M_TOT / 128);
    sgemm_kernel<1><<<g1, 256>>>(M_TOT, N_QKV, E_, x, w_qkv, nullptr, p_qkv);

    // 2) kv + ksum: split-S partials, then reduce (reduce also emits the
    //    kv tuple-tail output)
    const int total_needed = M_TOT * E_ + B_ * H_ * D_ * D_;
    const int write_tail = (out_size >= total_needed) ? 1 : 0;
    kv_partial_kernel<<<dim3(B_ * H_, SCH), 256>>>(p_qkv);
    kv_reduce_kernel<<<B_ * H_, 256>>>(out + (size_t)M_TOT * E_, write_tail);

    // 3) q @ kv, normalized by z
    attn_kernel<<<dim3(B_ * H_, S_ / 64), 256>>>(p_qkv);

    // 4) proj GEMM + bias -> d_out[0 : B*S*E)
    dim3 g2(E_ / 128, M_TOT / 128);
    sgemm_kernel<2><<<g2, 256>>>(M_TOT, E_, E_, p_attn, w_proj, b_proj, out);
}

// round 9
// speedup vs baseline: 2.8208x; 2.8208x over previous
#include <cuda_runtime.h>
#include <cuda_bf16.h>
#include <math.h>
#include <stdint.h>

// Problem constants (fixed by reference)
#define B_    8
#define S_    4096
#define E_    768
#define H_    12
#define D_    64
#define M_TOT (B_ * S_)      // 32768
#define N_QKV (3 * E_)       // 2304
#define K_    768
#define SCH   4

typedef __nv_bfloat16 bf16;

// ---------------- scratch (__device__ globals; no allocation allowed) -------
__device__ float g_qkv[(size_t)M_TOT * N_QKV];
__device__ float g_kv[B_ * H_ * D_ * D_];
__device__ float g_ksum[B_ * H_ * D_];
__device__ float g_kvp[SCH][B_ * H_ * D_ * D_];
__device__ float g_ksp[SCH][B_ * H_ * D_];
__device__ bf16 g_xh[(size_t)M_TOT * K_];
__device__ bf16 g_xl[(size_t)M_TOT * K_];
__device__ bf16 g_ah[(size_t)M_TOT * K_];         // attn result hi (written by attn_kernel)
__device__ bf16 g_al[(size_t)M_TOT * K_];         // attn result lo
__device__ bf16 g_wqh[(size_t)N_QKV * K_];        // w_qkv^T  [N][K]
__device__ bf16 g_wql[(size_t)N_QKV * K_];
__device__ bf16 g_wph[(size_t)E_ * K_];           // w_proj^T [N][K]
__device__ bf16 g_wpl[(size_t)E_ * K_];

// ---------------- baseline-ISA helpers (no 'a'-target features) -------------
__device__ __forceinline__ uint32_t smem_u32(const void* p) {
    uint32_t a;
    asm("{ .reg .u64 t; cvta.to.shared.u64 t, %1; cvt.u32.u64 %0, t; }"
        : "=r"(a) : "l"(p));
    return a;
}
__device__ __forceinline__ void cp_async16(uint32_t dst, const void* src) {
    asm volatile("cp.async.ca.shared.global [%0], [%1], 16;"
                 :: "r"(dst), "l"(src) : "memory");
}
__device__ __forceinline__ void cp_commit() {
    asm volatile("cp.async.commit_group;" ::: "memory");
}
__device__ __forceinline__ void cp_wait1() {
    asm volatile("cp.async.wait_group 1;" ::: "memory");
}
__device__ __forceinline__ void cp_wait0() {
    asm volatile("cp.async.wait_group 0;" ::: "memory");
}
__device__ __forceinline__ void ldsm4(uint32_t* r, uint32_t addr) {
    asm volatile("ldmatrix.sync.aligned.m8n8.x4.shared.b16 {%0,%1,%2,%3}, [%4];"
                 : "=r"(r[0]), "=r"(r[1]), "=r"(r[2]), "=r"(r[3]) : "r"(addr));
}
__device__ __forceinline__ void ldsm2(uint32_t* r, uint32_t addr) {
    asm volatile("ldmatrix.sync.aligned.m8n8.x2.shared.b16 {%0,%1}, [%2];"
                 : "=r"(r[0]), "=r"(r[1]) : "r"(addr));
}
__device__ __forceinline__ void mma_bf16(float* d, const uint32_t* a, const uint32_t* b) {
    asm volatile(
        "mma.sync.aligned.m16n8k16.row.col.f32.bf16.bf16.f32 "
        "{%0,%1,%2,%3}, {%4,%5,%6,%7}, {%8,%9}, {%0,%1,%2,%3};"
        : "+f"(d[0]), "+f"(d[1]), "+f"(d[2]), "+f"(d[3])
        : "r"(a[0]), "r"(a[1]), "r"(a[2]), "r"(a[3]), "r"(b[0]), "r"(b[1]));
}

// ---------------- prep: fp32 -> bf16 hi/lo split ----------------------------
__global__ __launch_bounds__(256) void split_kernel(
    const float* __restrict__ src, bf16* __restrict__ h, bf16* __restrict__ l)
{
    const size_t i4 = (size_t)blockIdx.x * 256 + threadIdx.x;
    float4 v = *(const float4*)(src + i4 * 4);
    bf16 hh[4], ll[4];
    float f[4] = {v.x, v.y, v.z, v.w};
#pragma unroll
    for (int j = 0; j < 4; j++) {
        hh[j] = __float2bfloat16(f[j]);
        ll[j] = __float2bfloat16(f[j] - __bfloat162float(hh[j]));
    }
    *(__nv_bfloat162*)(h + i4 * 4)     = __nv_bfloat162{hh[0], hh[1]};
    *(__nv_bfloat162*)(h + i4 * 4 + 2) = __nv_bfloat162{hh[2], hh[3]};
    *(__nv_bfloat162*)(l + i4 * 4)     = __nv_bfloat162{ll[0], ll[1]};
    *(__nv_bfloat162*)(l + i4 * 4 + 2) = __nv_bfloat162{ll[2], ll[3]};
}

// ---------------- prep: transpose [K,N] f32 -> [N,K] bf16 hi/lo -------------
__global__ __launch_bounds__(256) void trans_split_kernel(
    const float* __restrict__ w, bf16* __restrict__ th, bf16* __restrict__ tl,
    int K, int N)
{
    __shared__ float t[32][33];
    const int n0 = blockIdx.x * 32, k0 = blockIdx.y * 32;
    const int tx = threadIdx.x & 31, ty = threadIdx.x >> 5;
#pragma unroll
    for (int i = 0; i < 4; i++) {
        int r = ty + i * 8;
        t[r][tx] = w[(size_t)(k0 + r) * N + n0 + tx];
    }
    __syncthreads();
#pragma unroll
    for (int i = 0; i < 4; i++) {
        int r = ty + i * 8;
        float v = t[tx][r];
        bf16 h = __float2bfloat16(v);
        bf16 l = __float2bfloat16(v - __bfloat162float(h));
        th[(size_t)(n0 + r) * K + k0 + tx] = h;
        tl[(size_t)(n0 + r) * K + k0 + tx] = l;
    }
}

// ---------------------------------------------------------------------------
// bf16-split GEMM on mma.sync (HMMA): C[M,N] = A[M,K] @ B^T, B stored [N,K].
// CTA 128x128, 8 warps (2x4), warp tile 64x32. K chunks of 32 (2 k16 steps).
// 3 terms: AhBh + AhBl + AlBh, fp32 accum in registers.
// smem tiles [128][40] bf16 (pad 8: 80B row stride -> 8 distinct 16B banks
// mod 128 for ldmatrix, and 16B-aligned for cp.async).
// MODE 1: elu(c)+1 when n0 < 2E.  MODE 2: c += bias[col].
// ---------------------------------------------------------------------------
#define BKC    32
#define NCH    (K_ / BKC)          // 24
#define RSTR   40                  // smem row stride (bf16 elems)
#define TILE_E (128 * RSTR)        // 5120 elems per tile
#define BUF_E  (4 * TILE_E)        // Ah,Al,Bh,Bl
#define GEMM_SMEM (2 * BUF_E * 2)  // bytes = 81920

template <int MODE>
__global__ __launch_bounds__(256) void mma_gemm_kernel(
    int M, int N,
    const bf16* __restrict__ Ah, const bf16* __restrict__ Al,
    const bf16* __restrict__ Bh, const bf16* __restrict__ Bl,
    const float* __restrict__ bias, float* __restrict__ C)
{
    extern __shared__ bf16 smem[];
    const uint32_t sb = smem_u32(smem);
    const int tid = threadIdx.x, wid = tid >> 5, lane = tid & 31;
    const int n0 = blockIdx.x * 128, m0 = blockIdx.y * 128;
    const int m_w = (wid >> 2) * 64, n_w = (wid & 3) * 32;

    // cp.async assignment: idx -> (row, 16B-quad)
    const int crow = tid >> 2, cq = tid & 3;
    const bf16* srcs[4] = { Ah + (size_t)m0 * K_, Al + (size_t)m0 * K_,
                            Bh + (size_t)n0 * K_, Bl + (size_t)n0 * K_ };

    // ldmatrix per-lane bases (canonical m16n8k16 row.col recipe)
    const int a_row = m_w + (lane & 15), a_col = (lane >> 4) * 8;
    const int b_row = n_w + (lane & 7),  b_col = ((lane >> 3) & 1) * 8;

    float acc[4][4][4];
#pragma unroll
    for (int mi = 0; mi < 4; mi++)
#pragma unroll
        for (int ni = 0; ni < 4; ni++)
#pragma unroll
            for (int r = 0; r < 4; r++) acc[mi][ni][r] = 0.f;

    auto issue_chunk = [&](int c, int buf) {
        const int kc = c * BKC;
        const uint32_t bufb = sb + (uint32_t)buf * BUF_E * 2;
#pragma unroll
        for (int t = 0; t < 4; t++) {
#pragma unroll
            for (int i = 0; i < 2; i++) {
                const int row = crow + i * 64;
                const uint32_t dst =
                    bufb + (uint32_t)(t * TILE_E + row * RSTR + cq * 8) * 2;
                cp_async16(dst, srcs[t] + (size_t)row * K_ + kc + cq * 8);
            }
        }
        cp_commit();
    };

    issue_chunk(0, 0);
    for (int c = 0; c < NCH; c++) {
        const int buf = c & 1;
        const bool more = (c + 1 < NCH);
        if (more) issue_chunk(c + 1, buf ^ 1);
        if (more) cp_wait1(); else cp_wait0();
        __syncthreads();

        const uint32_t be = (uint32_t)buf * BUF_E;
#pragma unroll
        for (int ks = 0; ks < 2; ks++) {
            uint32_t ah[4][4], al[4][4], bh[4][2], bl[4][2];
#pragma unroll
            for (int mi = 0; mi < 4; mi++) {
                const uint32_t off = (uint32_t)((a_row + mi * 16) * RSTR + ks * 16 + a_col);
                ldsm4(ah[mi], sb + (be + off) * 2);
                ldsm4(al[mi], sb + (be + TILE_E + off) * 2);
            }
#pragma unroll
            for (int ni = 0; ni < 4; ni++) {
                const uint32_t off = (uint32_t)((b_row + ni * 8) * RSTR + ks * 16 + b_col);
                ldsm2(bh[ni], sb + (be + 2 * TILE_E + off) * 2);
                ldsm2(bl[ni], sb + (be + 3 * TILE_E + off) * 2);
            }
#pragma unroll
            for (int mi = 0; mi < 4; mi++)
#pragma unroll
                for (int ni = 0; ni < 4; ni++) {
                    mma_bf16(acc[mi][ni], ah[mi], bh[ni]);
                    mma_bf16(acc[mi][ni], ah[mi], bl[ni]);
                    mma_bf16(acc[mi][ni], al[mi], bh[ni]);
                }
        }
        __syncthreads();   // compute done before next prefetch overwrites buf
    }

    // ---- epilogue: lane holds D[g][2t],D[g][2t+1],D[g+8][2t],D[g+8][2t+1] ----
    const int g = lane >> 2, t4 = lane & 3;
    const bool act = (MODE == 1) && (n0 < 2 * E_);
#pragma unroll
    for (int mi = 0; mi < 4; mi++) {
#pragma unroll
        for (int ni = 0; ni < 4; ni++) {
            const int col = n0 + n_w + ni * 8 + 2 * t4;
            float v0 = acc[mi][ni][0], v1 = acc[mi][ni][1];
            float v2 = acc[mi][ni][2], v3 = acc[mi][ni][3];
            if (MODE == 1 && act) {
                v0 = (v0 > 0.f) ? (v0 + 1.f) : __expf(v0);
                v1 = (v1 > 0.f) ? (v1 + 1.f) : __expf(v1);
                v2 = (v2 > 0.f) ? (v2 + 1.f) : __expf(v2);
                v3 = (v3 > 0.f) ? (v3 + 1.f) : __expf(v3);
            }
            if (MODE == 2) {
                const float b0 = bias[col], b1 = bias[col + 1];
                v0 += b0; v1 += b1; v2 += b0; v3 += b1;
            }
            const int row = m0 + m_w + mi * 16 + g;
            *(float2*)(C + (size_t)row * N + col)       = float2{v0, v1};
            *(float2*)(C + (size_t)(row + 8) * N + col) = float2{v2, v3};
        }
    }
}

// ---------------------------------------------------------------------------
// kv partials (split-S) + reduce
// ---------------------------------------------------------------------------
__global__ __launch_bounds__(256) void kv_partial_kernel(const float* __restrict__ qkv)
{
    __shared__ float Ks[64][64];
    __shared__ float Vs[64][64];
    const int bh = blockIdx.x, sc = blockIdx.y;
    const int b = bh / H_, h = bh % H_;
    const int tid = threadIdx.x;
    const int ty = tid >> 4, tx = tid & 15;
    const float* kbase = qkv + (size_t)b * S_ * N_QKV + E_ + h * D_;
    const float* vbase = kbase + E_;
    float acc[4][4] = {};
    float ks[4] = {0.f, 0.f, 0.f, 0.f};
    const int s_beg = sc * (S_ / SCH), s_end = s_beg + S_ / SCH;
    for (int s0 = s_beg; s0 < s_end; s0 += 64) {
        __syncthreads();
#pragma unroll
        for (int i = 0; i < 4; i++) {
            int idx = tid + i * 256;
            int row = idx >> 4, c4 = idx & 15;
            *(float4*)&Ks[row][c4 * 4] =
                *(const float4*)(kbase + (size_t)(s0 + row) * N_QKV + c4 * 4);
            *(float4*)&Vs[row][c4 * 4] =
                *(const float4*)(vbase + (size_t)(s0 + row) * N_QKV + c4 * 4);
        }
        __syncthreads();
#pragma unroll 8
        for (int s = 0; s < 64; s++) {
            float4 av = *(float4*)&Ks[s][ty * 4];
            float4 bv = *(float4*)&Vs[s][tx * 4];
            float a[4] = {av.x, av.y, av.z, av.w};
            float bb[4] = {bv.x, bv.y, bv.z, bv.w};
            if (tx == 0) { ks[0] += a[0]; ks[1] += a[1]; ks[2] += a[2]; ks[3] += a[3]; }
#pragma unroll
            for (int i = 0; i < 4; i++)
#pragma unroll
                for (int j = 0; j < 4; j++)
                    acc[i][j] = fmaf(a[i], bb[j], acc[i][j]);
        }
    }
    float* kvp = g_kvp[sc] + (size_t)bh * D_ * D_;
#pragma unroll
    for (int i = 0; i < 4; i++)
#pragma unroll
        for (int j = 0; j < 4; j++)
            kvp[(ty * 4 + i) * D_ + tx * 4 + j] = acc[i][j];
    if (tx == 0) {
#pragma unroll
        for (int i = 0; i < 4; i++) g_ksp[sc][bh * D_ + ty * 4 + i] = ks[i];
    }
}

__global__ __launch_bounds__(256) void kv_reduce_kernel(
    float* __restrict__ out_tail, int write_tail)
{
    const int bh = blockIdx.x, tid = threadIdx.x;
    const size_t base = (size_t)bh * D_ * D_;
#pragma unroll
    for (int i = 0; i < 4; i++) {
        const int off = (tid + i * 256) * 4;
        float4 s = *(const float4*)(g_kvp[0] + base + off);
#pragma unroll
        for (int c = 1; c < SCH; c++) {
            float4 p = *(const float4*)(g_kvp[c] + base + off);
            s.x += p.x; s.y += p.y; s.z += p.z; s.w += p.w;
        }
        *(float4*)(g_kv + base + off) = s;
        if (write_tail) *(float4*)(out_tail + base + off) = s;
    }
    if (tid < D_) {
        float s = 0.f;
#pragma unroll
        for (int c = 0; c < SCH; c++) s += g_ksp[c][bh * D_ + tid];
        g_ksum[bh * D_ + tid] = s;
    }
}

// ---------------------------------------------------------------------------
// attn: v = z * (q @ kv); epilogue writes bf16 hi/lo split DIRECTLY into
// g_ah/g_al (proj GEMM A operands) — removes the separate split pass.
// ---------------------------------------------------------------------------
__global__ __launch_bounds__(256) void attn_kernel(const float* __restrict__ qkv)
{
    __shared__ float Qs[64][65];
    __shared__ float kvs[64][64];
    __shared__ float ksums[64];
    __shared__ float zs[64];
    const int bh = blockIdx.x;
    const int b = bh / H_, h = bh % H_;
    const int s0 = blockIdx.y * 64;
    const int tid = threadIdx.x;
    const float* qbase = qkv + (size_t)b * S_ * N_QKV + h * D_;
#pragma unroll
    for (int i = 0; i < 4; i++) {
        int idx = tid + i * 256;
        int row = idx >> 4, c4 = idx & 15;
        float4 v = *(const float4*)(qbase + (size_t)(s0 + row) * N_QKV + c4 * 4);
        Qs[row][c4 * 4 + 0] = v.x; Qs[row][c4 * 4 + 1] = v.y;
        Qs[row][c4 * 4 + 2] = v.z; Qs[row][c4 * 4 + 3] = v.w;
    }
#pragma unroll
    for (int i = 0; i < 4; i++) {
        int idx = tid + i * 256;
        int row = idx >> 4, c4 = idx & 15;
        *(float4*)&kvs[row][c4 * 4] =
            *(const float4*)(g_kv + (size_t)bh * 4096 + row * 64 + c4 * 4);
    }
    if (tid < 16)
        ((float4*)ksums)[tid] = ((const float4*)(g_ksum + bh * 64))[tid];
    __syncthreads();
    if (tid < 64) {
        float dot = 0.f;
#pragma unroll
        for (int k = 0; k < 64; k++) dot = fmaf(Qs[tid][k], ksums[k], dot);
        zs[tid] = 1.f / dot;
    }
    __syncthreads();
    const int ty = tid >> 3, tx = tid & 7;
    float acc[2][8] = {};
#pragma unroll 8
    for (int k = 0; k < 64; k++) {
        float a0 = Qs[ty * 2 + 0][k];
        float a1 = Qs[ty * 2 + 1][k];
        float4 bv0 = *(float4*)&kvs[k][tx * 8];
        float4 bv1 = *(float4*)&kvs[k][tx * 8 + 4];
        float bb[8] = {bv0.x, bv0.y, bv0.z, bv0.w, bv1.x, bv1.y, bv1.z, bv1.w};
#pragma unroll
        for (int j = 0; j < 8; j++) {
            acc[0][j] = fmaf(a0, bb[j], acc[0][j]);
            acc[1][j] = fmaf(a1, bb[j], acc[1][j]);
        }
    }
    // fused split epilogue: 8 contiguous bf16 (16B) per stream per row
    const size_t row_base = (size_t)(b * S_ + s0);
    const int coloff = h * D_ + tx * 8;
#pragma unroll
    for (int i = 0; i < 2; i++) {
        const int r = ty * 2 + i;
        const float z = zs[r];
        bf16 hv[8], lv[8];
#pragma unroll
        for (int j = 0; j < 8; j++) {
            const float v = acc[i][j] * z;
            hv[j] = __float2bfloat16(v);
            lv[j] = __float2bfloat16(v - __bfloat162float(hv[j]));
        }
        const size_t off = (row_base + r) * K_ + coloff;
        *(uint4*)(g_ah + off) = *(const uint4*)hv;
        *(uint4*)(g_al + off) = *(const uint4*)lv;
    }
}

// ---------------------------------------------------------------------------
extern "C" void kernel_launch(void* const* d_in, const int* in_sizes, int n_in,
                              void* d_out, int out_size)
{
    const float* x      = (const float*)d_in[0];
    const float* w_qkv  = (const float*)d_in[1];
    const float* w_proj = (const float*)d_in[2];
    const float* b_proj = (const float*)d_in[3];
    float* out = (float*)d_out;

    float* p_qkv = nullptr;
    bf16 *p_xh, *p_xl, *p_ah, *p_al, *p_wqh, *p_wql, *p_wph, *p_wpl;
    cudaGetSymbolAddress((void**)&p_qkv, g_qkv);
    cudaGetSymbolAddress((void**)&p_xh, g_xh);
    cudaGetSymbolAddress((void**)&p_xl, g_xl);
    cudaGetSymbolAddress((void**)&p_ah, g_ah);
    cudaGetSymbolAddress((void**)&p_al, g_al);
    cudaGetSymbolAddress((void**)&p_wqh, g_wqh);
    cudaGetSymbolAddress((void**)&p_wql, g_wql);
    cudaGetSymbolAddress((void**)&p_wph, g_wph);
    cudaGetSymbolAddress((void**)&p_wpl, g_wpl);

    // Idempotent, host-side, executes immediately (capture-safe); no static guard.
    cudaFuncSetAttribute(mma_gemm_kernel<1>,
                         cudaFuncAttributeMaxDynamicSharedMemorySize, GEMM_SMEM);
    cudaFuncSetAttribute(mma_gemm_kernel<2>,
                         cudaFuncAttributeMaxDynamicSharedMemorySize, GEMM_SMEM);

    // 0) operand prep
    split_kernel<<<(M_TOT * K_) / 1024, 256>>>(x, p_xh, p_xl);
    trans_split_kernel<<<dim3(N_QKV / 32, K_ / 32), 256>>>(w_qkv, p_wqh, p_wql, K_, N_QKV);
    trans_split_kernel<<<dim3(E_ / 32, K_ / 32), 256>>>(w_proj, p_wph, p_wpl, K_, E_);

    // 1) qkv GEMM (bf16x3 mma.sync) + fused elu(.)+1 on q,k columns
    mma_gemm_kernel<1><<<dim3(N_QKV / 128, M_TOT / 128), 256, GEMM_SMEM>>>(
        M_TOT, N_QKV, p_xh, p_xl, p_wqh, p_wql, nullptr, p_qkv);

    // 2) kv + ksum
    const int total_needed = M_TOT * E_ + B_ * H_ * D_ * D_;
    const int write_tail = (out_size >= total_needed) ? 1 : 0;
    kv_partial_kernel<<<dim3(B_ * H_, SCH), 256>>>(p_qkv);
    kv_reduce_kernel<<<B_ * H_, 256>>>(out + (size_t)M_TOT * E_, write_tail);

    // 3) q @ kv normalized by z, with fused bf16 hi/lo split output
    attn_kernel<<<dim3(B_ * H_, S_ / 64), 256>>>(p_qkv);

    // 4) proj GEMM (bf16x3 mma.sync) + bias
    mma_gemm_kernel<2><<<dim3(E_ / 128, M_TOT / 128), 256, GEMM_SMEM>>>(
        M_TOT, E_, p_ah, p_al, p_wph, p_wpl, b_proj, out);
}